// round 14
// baseline (speedup 1.0000x reference)
#include <cuda_runtime.h>
#include <cuda_bf16.h>
#include <mma.h>

using namespace nvcuda;
typedef unsigned int u32;
typedef unsigned char u8;
typedef __nv_bfloat16 bf16;

#define NITER 21        // floor(1/0.05)=20 scaled steps + 1 unscaled add
#define DT    0.05f
#define THREADS 256

// ---- global images ----
#define XN (8192u*384u)
#define HN (8192u*512u)
__device__ __align__(16) bf16 g_X [2u*XN];        // [m][384] hi | lo
__device__ __align__(16) bf16 g_H1[2u*HN];        // [m][512] hi | lo
__device__ __align__(16) bf16 g_H2[2u*HN];
__device__ __align__(16) bf16 g_W1[2u*196608u];   // [512 n][384 k] hi | lo
__device__ __align__(16) bf16 g_W2[2u*262144u];   // [512 n][512 k]
__device__ __align__(16) bf16 g_W3[2u*131072u];   // [256 n][512 k]
__device__ float g_State[8192u*256u];             // exact fp32 state [m][s]
__device__ u32   g_flag[256];                     // pair handshake counters

// ---- smem (bytes). rows padded to 40 bf16 (80B): LDSM conflict-free ----
#define SA_B    0u
#define SA_PRT  5120u     // 64 rows x 80B
#define SA_BUF  10240u
#define SB_B    20480u    // 2 buf x 2 part x NR rows x 80B (NR<=256)
#define SNC_B   102400u   // bounce: 8 warps x 1KB
#define SMEM_SZ 110592

using FragA = wmma::fragment<wmma::matrix_a, 16, 16, 16, bf16, wmma::row_major>;
using FragB = wmma::fragment<wmma::matrix_b, 16, 16, 16, bf16, wmma::col_major>;
using FragC = wmma::fragment<wmma::accumulator, 16, 16, 16, float>;

__device__ __forceinline__ void cp16ca(u32 dst, const void* src) {   // weights
    asm volatile("cp.async.ca.shared.global [%0], [%1], 16;" :: "r"(dst), "l"(src));
}
__device__ __forceinline__ void cp16cg(u32 dst, const void* src) {   // activations (L1 bypass)
    asm volatile("cp.async.cg.shared.global [%0], [%1], 16;" :: "r"(dst), "l"(src));
}
#define CP_COMMIT() asm volatile("cp.async.commit_group;" ::: "memory")
#define CP_WAIT0()  asm volatile("cp.async.wait_group 0;" ::: "memory")

__device__ __forceinline__ void bsplit(float v, bf16& h, bf16& l) {
    h = __float2bfloat16(v);
    l = __float2bfloat16(v - __bfloat162float(h));
}

// ---------- merged prep kernel (also zeroes pair flags) ----------
__global__ void prep_all(const float* __restrict__ state, const float* __restrict__ user,
                         const float* __restrict__ W1, const float* __restrict__ W2,
                         const float* __restrict__ W3) {
    u32 i = blockIdx.x * blockDim.x + threadIdx.x;
    if (i < 256u) g_flag[i] = 0u;
    if (i < 196608u) {
        u32 k = i >> 9, n = i & 511u;
        bf16 h, l; bsplit(W1[i], h, l);
        g_W1[n*384u + k] = h; g_W1[196608u + n*384u + k] = l;
    }
    if (i < 262144u) {
        u32 k = i >> 9, n = i & 511u;
        bf16 h, l; bsplit(W2[i], h, l);
        g_W2[n*512u + k] = h; g_W2[262144u + n*512u + k] = l;
    }
    if (i < 131072u) {
        u32 k = i >> 8, n = i & 255u;
        bf16 h, l; bsplit(W3[i], h, l);
        g_W3[n*512u + k] = h; g_W3[131072u + n*512u + k] = l;
    }
    if (i < 8192u*384u) {
        u32 m = i / 384u, f = i - m*384u;
        float v;
        if (f < 256u) { v = state[m*256u + f]; g_State[m*256u + f] = v; }
        else          { v = user[m*128u + (f - 256u)]; }
        bf16 h, l; bsplit(v, h, l);
        g_X[i] = h; g_X[XN + i] = l;
    }
}

// ---------- pair sync (adjacent CTAs share an m-tile) ----------
__device__ __forceinline__ void pair_sync(u32 cta, int phase, u32 tid) {
    __syncthreads();
    if (tid == 0) {
        __threadfence();
        atomicAdd(&g_flag[cta], 1u);
        u32 v;
        do {
            asm volatile("ld.global.acquire.gpu.u32 %0, [%1];"
                         : "=r"(v) : "l"(&g_flag[cta ^ 1u]));
        } while ((int)v < phase);
    }
    __syncthreads();
}

// ---------- staging ----------
__device__ __forceinline__ void stageA(u32 dst, const bf16* __restrict__ img,
                                       u32 ldk, u32 partN, u32 m0, u32 k0, u32 tid) {
#pragma unroll
    for (u32 e = 0; e < 2; ++e) {       // 512 chunks / 256 threads
        u32 idx = tid + e*256u;
        u32 p = idx >> 8, r = (idx >> 2) & 63u, ch = idx & 3u;
        cp16cg(dst + p*SA_PRT + r*80u + ch*16u,
               img + (size_t)p*partN + (size_t)(m0 + r)*ldk + k0 + ch*8u);
    }
}
template<u32 NR>
__device__ __forceinline__ void stageB(u32 dst, const bf16* __restrict__ img,
                                       u32 ldk, u32 partN, u32 n0, u32 k0, u32 tid) {
#pragma unroll
    for (u32 e = 0; e < NR/32u; ++e) {  // NR*8 chunks / 256 threads
        u32 idx = tid + e*256u;
        u32 p = idx / (NR*4u), rem = idx % (NR*4u), n = rem >> 2, ch = idx & 3u;
        cp16ca(dst + p*(NR*80u) + n*80u + ch*16u,
               img + (size_t)p*partN + (size_t)(n0 + n)*ldk + k0 + ch*8u);
    }
}

// ---------- GEMM: C[64 x NR] = A[64 x NST*32] * B^T, bf16 3-split ----------
// 8 warps: 2 rowgroups (32m) x 4 colgroups. Term-major MMA order for acc ILP.
template<int NST, int NT, u32 NR>
__device__ __forceinline__ void run_layer(
    const bf16* __restrict__ Aimg, u32 aldk, u32 apartN,
    const bf16* __restrict__ Bimg, u32 bldk, u32 bpartN, u32 n0,
    u32 m0, u8* smp, u32 smb, u32 tid, FragC (&c)[8])
{
#pragma unroll
    for (int i = 0; i < 2*NT; ++i) wmma::fill_fragment(c[i], 0.0f);
    const u32 warp = tid >> 5;
    const u32 rowg = warp >> 2, colg = warp & 3u;

    stageA(smb + SA_B, Aimg, aldk, apartN, m0, 0u, tid);
    stageB<NR>(smb + SB_B, Bimg, bldk, bpartN, n0, 0u, tid);
    CP_COMMIT();
#pragma unroll 1
    for (int st = 0; st < NST; ++st) {
        const u32 buf = (u32)st & 1u;
        CP_WAIT0();
        __syncthreads();
        if (st + 1 < NST) {
            stageA(smb + SA_B + (buf^1u)*SA_BUF, Aimg, aldk, apartN, m0, (u32)(st+1)*32u, tid);
            stageB<NR>(smb + SB_B + (buf^1u)*(NR*160u), Bimg, bldk, bpartN, n0, (u32)(st+1)*32u, tid);
            CP_COMMIT();
        }
        const bf16* sa = (const bf16*)(smp + SA_B + buf*SA_BUF);
        const bf16* sb = (const bf16*)(smp + SB_B + buf*(NR*160u));
#pragma unroll
        for (int ks = 0; ks < 2; ++ks) {
            FragA ah[2], al[2];
#pragma unroll
            for (int r2 = 0; r2 < 2; ++r2) {
                const bf16* ap = sa + (rowg*32u + (u32)r2*16u)*40u + (u32)ks*16u;
                wmma::load_matrix_sync(ah[r2], ap, 40);
                wmma::load_matrix_sync(al[r2], ap + 2560u, 40);        // A lo (+5120B)
            }
            // process t in pairs; term-major order => same-acc separation = 4 MMAs
#pragma unroll
            for (int t0 = 0; t0 < NT; t0 += 2) {
                const bf16* bp0 = sb + (colg*(u32)NT*16u + (u32)t0*16u)*40u + (u32)ks*16u;
                const bf16* bp1 = bp0 + 640u;                          // next 16 cols
                FragB bh0, bh1, bl0, bl1;
                wmma::load_matrix_sync(bh0, bp0, 40);
                wmma::load_matrix_sync(bh1, bp1, 40);
                // term 1: ah x bh (4 independent accumulators)
                wmma::mma_sync(c[t0],        ah[0], bh0, c[t0]);
                wmma::mma_sync(c[NT + t0],   ah[1], bh0, c[NT + t0]);
                wmma::mma_sync(c[t0+1],      ah[0], bh1, c[t0+1]);
                wmma::mma_sync(c[NT + t0+1], ah[1], bh1, c[NT + t0+1]);
                // term 2: al x bh (bh dies after this block)
                wmma::mma_sync(c[t0],        al[0], bh0, c[t0]);
                wmma::mma_sync(c[NT + t0],   al[1], bh0, c[NT + t0]);
                wmma::mma_sync(c[t0+1],      al[0], bh1, c[t0+1]);
                wmma::mma_sync(c[NT + t0+1], al[1], bh1, c[NT + t0+1]);
                // term 3: ah x bl
                wmma::load_matrix_sync(bl0, bp0 + (NR*40u), 40);       // B lo (+NR*80B)
                wmma::load_matrix_sync(bl1, bp1 + (NR*40u), 40);
                wmma::mma_sync(c[t0],        ah[0], bl0, c[t0]);
                wmma::mma_sync(c[NT + t0],   ah[1], bl0, c[NT + t0]);
                wmma::mma_sync(c[t0+1],      ah[0], bl1, c[t0+1]);
                wmma::mma_sync(c[NT + t0+1], ah[1], bl1, c[NT + t0+1]);
            }
        }
    }
}

// ---------- epilogues ----------
__device__ __forceinline__ void epiH(FragC (&c)[8], const float* __restrict__ bias,
                                     bf16* __restrict__ img, float* __restrict__ bounce,
                                     u32 tid, u32 m0, u32 c0) {
    u32 warp = tid >> 5, lane = tid & 31u;
    u32 rowg = warp >> 2, colg = warp & 3u;
    float* bw = bounce + warp*256u;
    u32 row = lane & 15u, cg = lane >> 4;
#pragma unroll
    for (int r2 = 0; r2 < 2; ++r2)
#pragma unroll 1
    for (int t = 0; t < 4; ++t) {
        wmma::store_matrix_sync(bw, c[r2*4 + t], 16, wmma::mem_row_major);
        __syncwarp();
        const float* p = bw + row*16u + cg*8u;
        u32 col = c0 + colg*64u + (u32)t*16u + cg*8u;
        u32 m = m0 + rowg*32u + (u32)r2*16u + row;
        float4 bA = __ldg((const float4*)(bias + col));
        float4 bB = __ldg((const float4*)(bias + col + 4));
        float bb[8] = { bA.x, bA.y, bA.z, bA.w, bB.x, bB.y, bB.z, bB.w };
        alignas(16) bf16 hv[8], lv[8];
#pragma unroll
        for (int j = 0; j < 8; ++j) {
            float v = p[j] + bb[j];
            v = v / (1.0f + __expf(-v));          // SiLU
            bsplit(v, hv[j], lv[j]);
        }
        size_t gi = (size_t)m*512u + col;
        *reinterpret_cast<uint4*>(&img[gi])      = *reinterpret_cast<const uint4*>(hv);
        *reinterpret_cast<uint4*>(&img[HN + gi]) = *reinterpret_cast<const uint4*>(lv);
        __syncwarp();
    }
}

__device__ __forceinline__ void epi3(FragC (&c)[8], const float* __restrict__ b3,
                                     float coef, bool last, float* __restrict__ out,
                                     float* __restrict__ bounce, u32 tid, u32 m0, u32 c0) {
    u32 warp = tid >> 5, lane = tid & 31u;
    u32 rowg = warp >> 2, colg = warp & 3u;
    float* bw = bounce + warp*256u;
    u32 row = lane & 15u, cg = lane >> 4;
#pragma unroll
    for (int r2 = 0; r2 < 2; ++r2)
#pragma unroll 1
    for (int t = 0; t < 2; ++t) {
        wmma::store_matrix_sync(bw, c[r2*2 + t], 16, wmma::mem_row_major);
        __syncwarp();
        const float* p = bw + row*16u + cg*8u;
        u32 col = c0 + colg*32u + (u32)t*16u + cg*8u;
        u32 m = m0 + rowg*32u + (u32)r2*16u + row;
        float4 bA = __ldg((const float4*)(b3 + col));
        float4 bB = __ldg((const float4*)(b3 + col + 4));
        float bb[8] = { bA.x, bA.y, bA.z, bA.w, bB.x, bB.y, bB.z, bB.w };
        alignas(16) bf16 hv[8], lv[8];
#pragma unroll
        for (int j = 0; j < 8; ++j) {
            float x = p[j] + bb[j];
            size_t si = (size_t)m*256u + col + j;
            float s = g_State[si] + coef * x;      // exact fp32 Euler recurrence
            g_State[si] = s;
            if (last) out[si] = s;
            bsplit(s, hv[j], lv[j]);
        }
        size_t gi = (size_t)m*384u + col;          // state region of X image
        *reinterpret_cast<uint4*>(&g_X[gi])      = *reinterpret_cast<const uint4*>(hv);
        *reinterpret_cast<uint4*>(&g_X[XN + gi]) = *reinterpret_cast<const uint4*>(lv);
        __syncwarp();
    }
}

// ---------- main kernel: pair of CTAs per 64-row m-tile, N split in half ----------
__global__ void __launch_bounds__(THREADS, 2)
ode_mma(const float* __restrict__ b1, const float* __restrict__ b2,
        const float* __restrict__ b3, float* __restrict__ out) {
    extern __shared__ __align__(16) u8 smp[];
    u32 smb = (u32)__cvta_generic_to_shared(smp);
    u32 tid = threadIdx.x;
    u32 cta = blockIdx.x;
    u32 m0   = (cta >> 1) * 64u;
    u32 half = cta & 1u;
    float* bounce = (float*)(smp + SNC_B);

    FragC c[8];
    int phase = 0;
#pragma unroll 1
    for (int it = 0; it < NITER; ++it) {
        const float coef = (it == NITER - 1) ? 1.0f : DT;
        // Layer 1: X[64,384] @ W1 cols [half*256, +256)
        run_layer<12, 4, 256u>(g_X, 384u, XN, g_W1, 384u, 196608u, half*256u,
                               m0, smp, smb, tid, c);
        epiH(c, b1, g_H1, bounce, tid, m0, half*256u);
        pair_sync(cta, ++phase, tid);
        // Layer 2: H1[64,512] @ W2 cols [half*256, +256)
        run_layer<16, 4, 256u>(g_H1, 512u, HN, g_W2, 512u, 262144u, half*256u,
                               m0, smp, smb, tid, c);
        epiH(c, b2, g_H2, bounce, tid, m0, half*256u);
        pair_sync(cta, ++phase, tid);
        // Layer 3: H2[64,512] @ W3 cols [half*128, +128) -> Euler update
        run_layer<16, 2, 128u>(g_H2, 512u, HN, g_W3, 512u, 131072u, half*128u,
                               m0, smp, smb, tid, c);
        epi3(c, b3, coef, it == NITER - 1, out, bounce, tid, m0, half*128u);
        pair_sync(cta, ++phase, tid);
    }
}

extern "C" void kernel_launch(void* const* d_in, const int* in_sizes, int n_in,
                              void* d_out, int out_size) {
    const float* state = (const float*)d_in[0];
    const float* user  = (const float*)d_in[1];
    const float* W1    = (const float*)d_in[2];
    const float* b1    = (const float*)d_in[3];
    const float* W2    = (const float*)d_in[4];
    const float* b2    = (const float*)d_in[5];
    const float* W3    = (const float*)d_in[6];
    const float* b3    = (const float*)d_in[7];
    float* out = (float*)d_out;

    prep_all<<<12288, 256>>>(state, user, W1, W2, W3);
    cudaFuncSetAttribute(ode_mma, cudaFuncAttributeMaxDynamicSharedMemorySize, SMEM_SZ);
    ode_mma<<<256, THREADS, SMEM_SZ>>>(b1, b2, b3, out);
}

// round 15
// speedup vs baseline: 1.0923x; 1.0923x over previous
#include <cuda_runtime.h>
#include <cuda_bf16.h>
#include <mma.h>

using namespace nvcuda;
typedef unsigned int u32;
typedef unsigned char u8;
typedef __nv_bfloat16 bf16;

#define NITER 21        // floor(1/0.05)=20 scaled steps + 1 unscaled add
#define DT    0.05f
#define THREADS 256

// ---- global images ----
#define XN (8192u*384u)
#define HN (8192u*512u)
__device__ __align__(16) bf16 g_X  [2u*XN];        // [m][384] hi | lo (init only)
__device__ __align__(16) bf16 g_H1 [2u*HN];        // [m][512] hi | lo
__device__ __align__(16) bf16 g_H2 [2u*HN];
__device__ __align__(16) bf16 g_W1 [2u*196608u];   // [512 n][384 k] hi | lo
__device__ __align__(16) bf16 g_W2 [2u*262144u];   // [512 n][512 k]
__device__ __align__(16) bf16 g_W31[2u*262144u];   // fused W3@W1s, [512 n][512 k]
__device__ __align__(16) bf16 g_W3 [2u*131072u];   // [256 n][512 k]
__device__ float g_W31f[262144u];                  // fp32 W3@W1s [k=512][n=512]
__device__ float g_c31 [512u];                     // b3@W1s
__device__ float g_h1p [8192u*512u];               // evolving h1_pre, fp32
__device__ float g_Sacc[8192u*512u];               // sum coef_i * H2_i, fp32
__device__ u32   g_flag[256];                      // pair handshake counters

// ---- smem (bytes). rows padded to 40 bf16 (80B): LDSM conflict-free ----
#define SA_B    0u
#define SA_PRT  5120u
#define SA_BUF  10240u
#define SB_B    20480u
#define SNC_B   102400u
#define SMEM_SZ 110592

using FragA = wmma::fragment<wmma::matrix_a, 16, 16, 16, bf16, wmma::row_major>;
using FragB = wmma::fragment<wmma::matrix_b, 16, 16, 16, bf16, wmma::col_major>;
using FragC = wmma::fragment<wmma::accumulator, 16, 16, 16, float>;

__device__ __forceinline__ void cp16ca(u32 dst, const void* src) {
    asm volatile("cp.async.ca.shared.global [%0], [%1], 16;" :: "r"(dst), "l"(src));
}
__device__ __forceinline__ void cp16cg(u32 dst, const void* src) {
    asm volatile("cp.async.cg.shared.global [%0], [%1], 16;" :: "r"(dst), "l"(src));
}
#define CP_COMMIT() asm volatile("cp.async.commit_group;" ::: "memory")
#define CP_WAIT0()  asm volatile("cp.async.wait_group 0;" ::: "memory")

__device__ __forceinline__ void bsplit(float v, bf16& h, bf16& l) {
    h = __float2bfloat16(v);
    l = __float2bfloat16(v - __bfloat162float(h));
}
__device__ __forceinline__ float silu(float x) { return x / (1.0f + __expf(-x)); }

// ---------- prep 1: fused weight W31 = W3 @ W1s, c31 = b3 @ W1s (fp32) ----------
__global__ void prep_w31(const float* __restrict__ W1, const float* __restrict__ W3,
                         const float* __restrict__ b3) {
    u32 n = threadIdx.x;          // h1 column
    u32 k = blockIdx.x;           // H2 index (or 512 => c31)
    float a = 0.0f;
    if (k < 512u) {
#pragma unroll 8
        for (u32 s = 0; s < 256u; ++s) a += W3[k*256u + s] * W1[s*512u + n];
        g_W31f[k*512u + n] = a;
    } else {
#pragma unroll 8
        for (u32 s = 0; s < 256u; ++s) a += b3[s] * W1[s*512u + n];
        g_c31[n] = a;
    }
}

// ---------- prep 2: split images, X image, zero Sacc/flags ----------
__global__ void prep_all(const float* __restrict__ state, const float* __restrict__ user,
                         const float* __restrict__ W1, const float* __restrict__ W2,
                         const float* __restrict__ W3) {
    u32 i = blockIdx.x * blockDim.x + threadIdx.x;
    if (i < 256u) g_flag[i] = 0u;
    if (i < 8192u*512u) g_Sacc[i] = 0.0f;
    if (i < 196608u) {
        u32 k = i >> 9, n = i & 511u;
        bf16 h, l; bsplit(W1[i], h, l);
        g_W1[n*384u + k] = h; g_W1[196608u + n*384u + k] = l;
    }
    if (i < 262144u) {
        u32 k = i >> 9, n = i & 511u;
        bf16 h, l; bsplit(W2[i], h, l);
        g_W2[n*512u + k] = h; g_W2[262144u + n*512u + k] = l;
        bf16 h2, l2; bsplit(g_W31f[i], h2, l2);
        g_W31[n*512u + k] = h2; g_W31[262144u + n*512u + k] = l2;
    }
    if (i < 131072u) {
        u32 k = i >> 8, n = i & 255u;
        bf16 h, l; bsplit(W3[i], h, l);
        g_W3[n*512u + k] = h; g_W3[131072u + n*512u + k] = l;
    }
    if (i < 8192u*384u) {
        u32 m = i / 384u, f = i - m*384u;
        float v = (f < 256u) ? state[m*256u + f] : user[m*128u + (f - 256u)];
        bf16 h, l; bsplit(v, h, l);
        g_X[i] = h; g_X[XN + i] = l;
    }
}

// ---------- pair sync ----------
__device__ __forceinline__ void pair_sync(u32 cta, int phase, u32 tid) {
    __syncthreads();
    if (tid == 0) {
        __threadfence();
        atomicAdd(&g_flag[cta], 1u);
        u32 v;
        do {
            asm volatile("ld.global.acquire.gpu.u32 %0, [%1];"
                         : "=r"(v) : "l"(&g_flag[cta ^ 1u]));
        } while ((int)v < phase);
    }
    __syncthreads();
}

// ---------- staging ----------
__device__ __forceinline__ void stageA(u32 dst, const bf16* __restrict__ img,
                                       u32 ldk, u32 partN, u32 m0, u32 k0, u32 tid) {
#pragma unroll
    for (u32 e = 0; e < 2; ++e) {
        u32 idx = tid + e*256u;
        u32 p = idx >> 8, r = (idx >> 2) & 63u, ch = idx & 3u;
        cp16cg(dst + p*SA_PRT + r*80u + ch*16u,
               img + (size_t)p*partN + (size_t)(m0 + r)*ldk + k0 + ch*8u);
    }
}
template<u32 NR>
__device__ __forceinline__ void stageB(u32 dst, const bf16* __restrict__ img,
                                       u32 ldk, u32 partN, u32 n0, u32 k0, u32 tid) {
#pragma unroll
    for (u32 e = 0; e < NR/32u; ++e) {
        u32 idx = tid + e*256u;
        u32 p = idx / (NR*4u), rem = idx % (NR*4u), n = rem >> 2, ch = idx & 3u;
        cp16ca(dst + p*(NR*80u) + n*80u + ch*16u,
               img + (size_t)p*partN + (size_t)(n0 + n)*ldk + k0 + ch*8u);
    }
}

// ---------- GEMM: C[64 x NR] = A[64 x NST*32] * B^T, bf16 3-split ----------
template<int NST, int NT, u32 NR>
__device__ __forceinline__ void run_layer(
    const bf16* __restrict__ Aimg, u32 aldk, u32 apartN,
    const bf16* __restrict__ Bimg, u32 bldk, u32 bpartN, u32 n0,
    u32 m0, u8* smp, u32 smb, u32 tid, FragC (&c)[8])
{
#pragma unroll
    for (int i = 0; i < 2*NT; ++i) wmma::fill_fragment(c[i], 0.0f);
    const u32 warp = tid >> 5;
    const u32 rowg = warp >> 2, colg = warp & 3u;

    stageA(smb + SA_B, Aimg, aldk, apartN, m0, 0u, tid);
    stageB<NR>(smb + SB_B, Bimg, bldk, bpartN, n0, 0u, tid);
    CP_COMMIT();
#pragma unroll 1
    for (int st = 0; st < NST; ++st) {
        const u32 buf = (u32)st & 1u;
        CP_WAIT0();
        __syncthreads();
        if (st + 1 < NST) {
            stageA(smb + SA_B + (buf^1u)*SA_BUF, Aimg, aldk, apartN, m0, (u32)(st+1)*32u, tid);
            stageB<NR>(smb + SB_B + (buf^1u)*(NR*160u), Bimg, bldk, bpartN, n0, (u32)(st+1)*32u, tid);
            CP_COMMIT();
        }
        const bf16* sa = (const bf16*)(smp + SA_B + buf*SA_BUF);
        const bf16* sb = (const bf16*)(smp + SB_B + buf*(NR*160u));
#pragma unroll
        for (int ks = 0; ks < 2; ++ks) {
            FragA ah[2], al[2];
#pragma unroll
            for (int r2 = 0; r2 < 2; ++r2) {
                const bf16* ap = sa + (rowg*32u + (u32)r2*16u)*40u + (u32)ks*16u;
                wmma::load_matrix_sync(ah[r2], ap, 40);
                wmma::load_matrix_sync(al[r2], ap + 2560u, 40);
            }
#pragma unroll
            for (int t = 0; t < NT; ++t) {
                const bf16* bp = sb + (colg*(u32)NT*16u + (u32)t*16u)*40u + (u32)ks*16u;
                FragB bh, bl;
                wmma::load_matrix_sync(bh, bp, 40);
                wmma::load_matrix_sync(bl, bp + (NR*40u), 40);
#pragma unroll
                for (int r2 = 0; r2 < 2; ++r2) {
                    wmma::mma_sync(c[r2*NT + t], ah[r2], bh, c[r2*NT + t]);
                    wmma::mma_sync(c[r2*NT + t], ah[r2], bl, c[r2*NT + t]);
                    wmma::mma_sync(c[r2*NT + t], al[r2], bh, c[r2*NT + t]);
                }
            }
        }
    }
}

// ---------- epilogue B (layer-2): silu + H2 image (+Sacc RMW) / last: Sacc image ----------
__device__ __forceinline__ void epiB(FragC (&c)[8], const float* __restrict__ b2,
                                     float coef, bool last, float* __restrict__ bounce,
                                     u32 tid, u32 m0, u32 c0) {
    u32 warp = tid >> 5, lane = tid & 31u;
    u32 rowg = warp >> 2, colg = warp & 3u;
    float* bw = bounce + warp*256u;
    u32 row = lane & 15u, cg = lane >> 4;
#pragma unroll
    for (int r2 = 0; r2 < 2; ++r2)
#pragma unroll 1
    for (int t = 0; t < 4; ++t) {
        wmma::store_matrix_sync(bw, c[r2*4 + t], 16, wmma::mem_row_major);
        __syncwarp();
        const float* p = bw + row*16u + cg*8u;
        u32 col = c0 + colg*64u + (u32)t*16u + cg*8u;
        u32 m = m0 + rowg*32u + (u32)r2*16u + row;
        float4 bA = __ldg((const float4*)(b2 + col));
        float4 bB = __ldg((const float4*)(b2 + col + 4));
        float bb[8] = { bA.x, bA.y, bA.z, bA.w, bB.x, bB.y, bB.z, bB.w };
        size_t si = (size_t)m*512u + col;
        float v[8];
#pragma unroll
        for (int j = 0; j < 8; ++j) v[j] = silu(p[j] + bb[j]);
        alignas(16) bf16 hv[8], lv[8];
        if (!last) {
            float4 s0 = *(float4*)(g_Sacc + si);
            float4 s1 = *(float4*)(g_Sacc + si + 4);
            s0.x += coef*v[0]; s0.y += coef*v[1]; s0.z += coef*v[2]; s0.w += coef*v[3];
            s1.x += coef*v[4]; s1.y += coef*v[5]; s1.z += coef*v[6]; s1.w += coef*v[7];
            *(float4*)(g_Sacc + si)     = s0;
            *(float4*)(g_Sacc + si + 4) = s1;
#pragma unroll
            for (int j = 0; j < 8; ++j) bsplit(v[j], hv[j], lv[j]);
            *reinterpret_cast<uint4*>(&g_H2[si])      = *reinterpret_cast<const uint4*>(hv);
            *reinterpret_cast<uint4*>(&g_H2[HN + si]) = *reinterpret_cast<const uint4*>(lv);
        } else {
            float4 s0 = *(float4*)(g_Sacc + si);
            float4 s1 = *(float4*)(g_Sacc + si + 4);
            float S[8] = { s0.x+v[0], s0.y+v[1], s0.z+v[2], s0.w+v[3],
                           s1.x+v[4], s1.y+v[5], s1.z+v[6], s1.w+v[7] };
#pragma unroll
            for (int j = 0; j < 8; ++j) bsplit(S[j], hv[j], lv[j]);
            // write Sacc image into g_H2 (dead at it=20): final GEMM A operand
            *reinterpret_cast<uint4*>(&g_H2[si])      = *reinterpret_cast<const uint4*>(hv);
            *reinterpret_cast<uint4*>(&g_H2[HN + si]) = *reinterpret_cast<const uint4*>(lv);
        }
        __syncwarp();
    }
}

// ---------- epilogue C (fused h1_pre update) / also init (plain write) ----------
__device__ __forceinline__ void epiC(FragC (&c)[8], const float* __restrict__ addv,
                                     float coef, bool init, float* __restrict__ bounce,
                                     u32 tid, u32 m0, u32 c0) {
    u32 warp = tid >> 5, lane = tid & 31u;
    u32 rowg = warp >> 2, colg = warp & 3u;
    float* bw = bounce + warp*256u;
    u32 row = lane & 15u, cg = lane >> 4;
#pragma unroll
    for (int r2 = 0; r2 < 2; ++r2)
#pragma unroll 1
    for (int t = 0; t < 4; ++t) {
        wmma::store_matrix_sync(bw, c[r2*4 + t], 16, wmma::mem_row_major);
        __syncwarp();
        const float* p = bw + row*16u + cg*8u;
        u32 col = c0 + colg*64u + (u32)t*16u + cg*8u;
        u32 m = m0 + rowg*32u + (u32)r2*16u + row;
        float4 bA = __ldg((const float4*)(addv + col));
        float4 bB = __ldg((const float4*)(addv + col + 4));
        float bb[8] = { bA.x, bA.y, bA.z, bA.w, bB.x, bB.y, bB.z, bB.w };
        size_t si = (size_t)m*512u + col;
        float hp[8];
        if (init) {
#pragma unroll
            for (int j = 0; j < 8; ++j) hp[j] = p[j] + bb[j];
        } else {
            float4 h0 = *(float4*)(g_h1p + si);
            float4 h1 = *(float4*)(g_h1p + si + 4);
            float ho[8] = { h0.x, h0.y, h0.z, h0.w, h1.x, h1.y, h1.z, h1.w };
#pragma unroll
            for (int j = 0; j < 8; ++j) hp[j] = ho[j] + coef * (p[j] + bb[j]);
        }
        *(float4*)(g_h1p + si)     = make_float4(hp[0], hp[1], hp[2], hp[3]);
        *(float4*)(g_h1p + si + 4) = make_float4(hp[4], hp[5], hp[6], hp[7]);
        alignas(16) bf16 hv[8], lv[8];
#pragma unroll
        for (int j = 0; j < 8; ++j) bsplit(silu(hp[j]), hv[j], lv[j]);
        *reinterpret_cast<uint4*>(&g_H1[si])      = *reinterpret_cast<const uint4*>(hv);
        *reinterpret_cast<uint4*>(&g_H1[HN + si]) = *reinterpret_cast<const uint4*>(lv);
        __syncwarp();
    }
}

// ---------- final epilogue: out = state0 + Sacc@W3 + 2*b3 ----------
__device__ __forceinline__ void epiF(FragC (&c)[8], const float* __restrict__ b3,
                                     const float* __restrict__ state0,
                                     float* __restrict__ out,
                                     float* __restrict__ bounce, u32 tid, u32 m0, u32 c0) {
    u32 warp = tid >> 5, lane = tid & 31u;
    u32 rowg = warp >> 2, colg = warp & 3u;
    float* bw = bounce + warp*256u;
    u32 row = lane & 15u, cg = lane >> 4;
#pragma unroll
    for (int r2 = 0; r2 < 2; ++r2)
#pragma unroll 1
    for (int t = 0; t < 2; ++t) {
        wmma::store_matrix_sync(bw, c[r2*2 + t], 16, wmma::mem_row_major);
        __syncwarp();
        const float* p = bw + row*16u + cg*8u;
        u32 col = c0 + colg*32u + (u32)t*16u + cg*8u;
        u32 m = m0 + rowg*32u + (u32)r2*16u + row;
        size_t si = (size_t)m*256u + col;
        float4 bA = __ldg((const float4*)(b3 + col));
        float4 bB = __ldg((const float4*)(b3 + col + 4));
        float4 s0 = __ldg((const float4*)(state0 + si));
        float4 s1 = __ldg((const float4*)(state0 + si + 4));
        float bb[8] = { bA.x, bA.y, bA.z, bA.w, bB.x, bB.y, bB.z, bB.w };
        float ss[8] = { s0.x, s0.y, s0.z, s0.w, s1.x, s1.y, s1.z, s1.w };
        float o[8];
#pragma unroll
        for (int j = 0; j < 8; ++j) o[j] = ss[j] + p[j] + 2.0f * bb[j];
        *(float4*)(out + si)     = make_float4(o[0], o[1], o[2], o[3]);
        *(float4*)(out + si + 4) = make_float4(o[4], o[5], o[6], o[7]);
        __syncwarp();
    }
}

// ---------- main kernel ----------
__global__ void __launch_bounds__(THREADS, 2)
ode_mma(const float* __restrict__ b1, const float* __restrict__ b2,
        const float* __restrict__ b3, const float* __restrict__ state0,
        float* __restrict__ out) {
    extern __shared__ __align__(16) u8 smp[];
    u32 smb = (u32)__cvta_generic_to_shared(smp);
    u32 tid = threadIdx.x;
    u32 cta = blockIdx.x;
    u32 m0   = (cta >> 1) * 64u;
    u32 half = cta & 1u;
    float* bounce = (float*)(smp + SNC_B);

    FragC c[8];
    int phase = 0;

    // init: h1_pre = X@W1 + b1  (also emits H1(0) image)
    run_layer<12, 4, 256u>(g_X, 384u, XN, g_W1, 384u, 196608u, half*256u,
                           m0, smp, smb, tid, c);
    epiC(c, b1, 0.0f, true, bounce, tid, m0, half*256u);
    pair_sync(cta, ++phase, tid);

#pragma unroll 1
    for (int it = 0; it < NITER; ++it) {
        const float coef = (it == NITER - 1) ? 1.0f : DT;
        const bool last = (it == NITER - 1);
        // H2 = silu(H1@W2 + b2); Sacc += coef*H2 (or emit Sacc image at last)
        run_layer<16, 4, 256u>(g_H1, 512u, HN, g_W2, 512u, 262144u, half*256u,
                               m0, smp, smb, tid, c);
        epiB(c, b2, coef, last, bounce, tid, m0, half*256u);
        pair_sync(cta, ++phase, tid);
        if (!last) {
            // h1_pre += coef*(H2@W31 + c31); emit H1(it+1) image
            run_layer<16, 4, 256u>(g_H2, 512u, HN, g_W31, 512u, 262144u, half*256u,
                                   m0, smp, smb, tid, c);
            epiC(c, g_c31, coef, false, bounce, tid, m0, half*256u);
            pair_sync(cta, ++phase, tid);
        }
    }

    // final: out = state0 + Sacc@W3 + 2*b3   (Sacc image lives in g_H2)
    run_layer<16, 2, 128u>(g_H2, 512u, HN, g_W3, 512u, 131072u, half*128u,
                           m0, smp, smb, tid, c);
    epiF(c, b3, state0, out, bounce, tid, m0, half*128u);
}

extern "C" void kernel_launch(void* const* d_in, const int* in_sizes, int n_in,
                              void* d_out, int out_size) {
    const float* state = (const float*)d_in[0];
    const float* user  = (const float*)d_in[1];
    const float* W1    = (const float*)d_in[2];
    const float* b1    = (const float*)d_in[3];
    const float* W2    = (const float*)d_in[4];
    const float* b2    = (const float*)d_in[5];
    const float* W3    = (const float*)d_in[6];
    const float* b3    = (const float*)d_in[7];
    float* out = (float*)d_out;

    prep_w31<<<513, 512>>>(W1, W3, b3);
    prep_all<<<16384, 256>>>(state, user, W1, W2, W3);
    cudaFuncSetAttribute(ode_mma, cudaFuncAttributeMaxDynamicSharedMemorySize, SMEM_SZ);
    ode_mma<<<256, THREADS, SMEM_SZ>>>(b1, b2, b3, state, out);
}

// round 16
// speedup vs baseline: 1.1846x; 1.0844x over previous
#include <cuda_runtime.h>
#include <cuda_bf16.h>
#include <cuda_fp16.h>
#include <mma.h>

using namespace nvcuda;
typedef unsigned int u32;
typedef unsigned char u8;
typedef __nv_bfloat16 bf16;

#define NITER 21        // floor(1/0.05)=20 scaled steps + 1 unscaled add
#define DT    0.05f
#define THREADS 256

// ---- global images ----
#define XN (8192u*384u)
#define HN (8192u*512u)
__device__ __align__(16) bf16   g_X  [2u*XN];       // [m][384] hi | lo (init only)
__device__ __align__(16) bf16   g_H1 [2u*HN];       // [m][512] bf16 hi | lo
__device__ __align__(16) __half g_H2h[2u*HN];       // [m][512] fp16 hi | lo (H2 / Sacc image)
__device__ __align__(16) bf16   g_W1 [2u*196608u];  // [512 n][384 k] hi | lo
__device__ __align__(16) bf16   g_W2 [2u*262144u];  // [512 n][512 k] hi | lo
__device__ __align__(16) __half g_W31h[262144u];    // fused W3@W1s, [512 n][512 k] fp16 single
__device__ __align__(16) __half g_W3h[2u*131072u];  // [256 n][512 k] fp16 hi | lo
__device__ float g_W31f[262144u];                   // fp32 W3@W1s [k=512][n=512]
__device__ float g_c31 [512u];                      // b3@W1s
__device__ float g_h1p [8192u*512u];                // evolving h1_pre, fp32
__device__ float g_Sacc[8192u*512u];                // sum coef_i * H2_i, fp32
__device__ u32   g_flag[256];                       // pair handshake counters

// ---- smem (bytes). rows padded to 40 elems (80B): LDSM conflict-free ----
#define SA_B    0u
#define SA_PRT  5120u
#define SA_BUF  10240u
#define SB_B    20480u
#define SNC_B   102400u
#define SMEM_SZ 110592

using FragC = wmma::fragment<wmma::accumulator, 16, 16, 16, float>;

__device__ __forceinline__ void cp16ca(u32 dst, const void* src) {
    asm volatile("cp.async.ca.shared.global [%0], [%1], 16;" :: "r"(dst), "l"(src));
}
__device__ __forceinline__ void cp16cg(u32 dst, const void* src) {
    asm volatile("cp.async.cg.shared.global [%0], [%1], 16;" :: "r"(dst), "l"(src));
}
#define CP_COMMIT() asm volatile("cp.async.commit_group;" ::: "memory")
#define CP_WAIT0()  asm volatile("cp.async.wait_group 0;" ::: "memory")

__device__ __forceinline__ void bsplit(float v, bf16& h, bf16& l) {
    h = __float2bfloat16(v);
    l = __float2bfloat16(v - __bfloat162float(h));
}
__device__ __forceinline__ void hsplit(float v, __half& h, __half& l) {
    h = __float2half_rn(v);
    l = __float2half_rn(v - __half2float(h));
}
__device__ __forceinline__ float silu(float x) { return x / (1.0f + __expf(-x)); }

// ---------- prep 1: fused weight W31 = W3 @ W1s, c31 = b3 @ W1s (fp32) ----------
__global__ void prep_w31(const float* __restrict__ W1, const float* __restrict__ W3,
                         const float* __restrict__ b3) {
    u32 n = threadIdx.x;
    u32 k = blockIdx.x;
    float a = 0.0f;
    if (k < 512u) {
#pragma unroll 8
        for (u32 s = 0; s < 256u; ++s) a += W3[k*256u + s] * W1[s*512u + n];
        g_W31f[k*512u + n] = a;
    } else {
#pragma unroll 8
        for (u32 s = 0; s < 256u; ++s) a += b3[s] * W1[s*512u + n];
        g_c31[n] = a;
    }
}

// ---------- prep 2: split images, X image, zero Sacc/flags ----------
__global__ void prep_all(const float* __restrict__ state, const float* __restrict__ user,
                         const float* __restrict__ W1, const float* __restrict__ W2,
                         const float* __restrict__ W3) {
    u32 i = blockIdx.x * blockDim.x + threadIdx.x;
    if (i < 256u) g_flag[i] = 0u;
    if (i < 8192u*512u) g_Sacc[i] = 0.0f;
    if (i < 196608u) {
        u32 k = i >> 9, n = i & 511u;
        bf16 h, l; bsplit(W1[i], h, l);
        g_W1[n*384u + k] = h; g_W1[196608u + n*384u + k] = l;
    }
    if (i < 262144u) {
        u32 k = i >> 9, n = i & 511u;
        bf16 h, l; bsplit(W2[i], h, l);
        g_W2[n*512u + k] = h; g_W2[262144u + n*512u + k] = l;
        g_W31h[n*512u + k] = __float2half_rn(g_W31f[i]);   // fp16 single
    }
    if (i < 131072u) {
        u32 k = i >> 8, n = i & 255u;
        __half h, l; hsplit(W3[i], h, l);
        g_W3h[n*512u + k] = h; g_W3h[131072u + n*512u + k] = l;
    }
    if (i < 8192u*384u) {
        u32 m = i / 384u, f = i - m*384u;
        float v = (f < 256u) ? state[m*256u + f] : user[m*128u + (f - 256u)];
        bf16 h, l; bsplit(v, h, l);
        g_X[i] = h; g_X[XN + i] = l;
    }
}

// ---------- pair sync ----------
__device__ __forceinline__ void pair_sync(u32 cta, int phase, u32 tid) {
    __syncthreads();
    if (tid == 0) {
        __threadfence();
        atomicAdd(&g_flag[cta], 1u);
        u32 v;
        do {
            asm volatile("ld.global.acquire.gpu.u32 %0, [%1];"
                         : "=r"(v) : "l"(&g_flag[cta ^ 1u]));
        } while ((int)v < phase);
    }
    __syncthreads();
}

// ---------- staging (element size 2B for both bf16 and fp16) ----------
__device__ __forceinline__ void stageA(u32 dst, const void* img,
                                       u32 ldk, u32 partN, u32 m0, u32 k0, u32 tid) {
#pragma unroll
    for (u32 e = 0; e < 2; ++e) {
        u32 idx = tid + e*256u;
        u32 p = idx >> 8, r = (idx >> 2) & 63u, ch = idx & 3u;
        cp16cg(dst + p*SA_PRT + r*80u + ch*16u,
               (const u8*)img + 2u*((size_t)p*partN + (size_t)(m0 + r)*ldk + k0 + ch*8u));
    }
}
template<u32 NR, int BP>
__device__ __forceinline__ void stageB(u32 dst, const void* img,
                                       u32 ldk, u32 partN, u32 n0, u32 k0, u32 tid) {
#pragma unroll
    for (u32 e = 0; e < NR*BP/64u; ++e) {
        u32 idx = tid + e*256u;
        u32 p = idx / (NR*4u), rem = idx % (NR*4u), n = rem >> 2, ch = rem & 3u;
        cp16ca(dst + p*(NR*80u) + n*80u + ch*16u,
               (const u8*)img + 2u*((size_t)p*partN + (size_t)(n0 + n)*ldk + k0 + ch*8u));
    }
}

// ---------- GEMM: C[64 x NR] = A[64 x NST*32] * B^T ----------
// TERMS=3: ah*bh + ah*bl + al*bh (B has 2 parts). TERMS=2: ah*b + al*b (B single).
template<typename T, int NST, int NT, u32 NR, int TERMS>
__device__ __forceinline__ void run_layer(
    const T* __restrict__ Aimg, u32 aldk, u32 apartN,
    const T* __restrict__ Bimg, u32 bldk, u32 bpartN, u32 n0,
    u32 m0, u8* smp, u32 smb, u32 tid, FragC (&c)[8])
{
    constexpr int BP = (TERMS == 3) ? 2 : 1;
    constexpr u32 BUFSZ = NR * 80u * (u32)BP;
#pragma unroll
    for (int i = 0; i < 2*NT; ++i) wmma::fill_fragment(c[i], 0.0f);
    const u32 warp = tid >> 5;
    const u32 rowg = warp >> 2, colg = warp & 3u;

    stageA(smb + SA_B, Aimg, aldk, apartN, m0, 0u, tid);
    stageB<NR, BP>(smb + SB_B, Bimg, bldk, bpartN, n0, 0u, tid);
    CP_COMMIT();
#pragma unroll 1
    for (int st = 0; st < NST; ++st) {
        const u32 buf = (u32)st & 1u;
        CP_WAIT0();
        __syncthreads();
        if (st + 1 < NST) {
            stageA(smb + SA_B + (buf^1u)*SA_BUF, Aimg, aldk, apartN, m0, (u32)(st+1)*32u, tid);
            stageB<NR, BP>(smb + SB_B + (buf^1u)*BUFSZ, Bimg, bldk, bpartN, n0, (u32)(st+1)*32u, tid);
            CP_COMMIT();
        }
        const T* sa = (const T*)(smp + SA_B + buf*SA_BUF);
        const T* sb = (const T*)(smp + SB_B + buf*BUFSZ);
#pragma unroll
        for (int ks = 0; ks < 2; ++ks) {
            wmma::fragment<wmma::matrix_a, 16, 16, 16, T, wmma::row_major> ah[2], al[2];
#pragma unroll
            for (int r2 = 0; r2 < 2; ++r2) {
                const T* ap = sa + (rowg*32u + (u32)r2*16u)*40u + (u32)ks*16u;
                wmma::load_matrix_sync(ah[r2], ap, 40);
                wmma::load_matrix_sync(al[r2], ap + 2560u, 40);       // A lo (+5120B)
            }
#pragma unroll
            for (int t = 0; t < NT; ++t) {
                const T* bp = sb + (colg*(u32)NT*16u + (u32)t*16u)*40u + (u32)ks*16u;
                wmma::fragment<wmma::matrix_b, 16, 16, 16, T, wmma::col_major> bh, bl;
                wmma::load_matrix_sync(bh, bp, 40);
                if (TERMS == 3) wmma::load_matrix_sync(bl, bp + (NR*40u), 40);
#pragma unroll
                for (int r2 = 0; r2 < 2; ++r2) {
                    wmma::mma_sync(c[r2*NT + t], ah[r2], bh, c[r2*NT + t]);
                    if (TERMS == 3) wmma::mma_sync(c[r2*NT + t], ah[r2], bl, c[r2*NT + t]);
                    wmma::mma_sync(c[r2*NT + t], al[r2], bh, c[r2*NT + t]);
                }
            }
        }
    }
}

// ---------- epilogue B (layer-2): silu + fp16 H2 image (+Sacc RMW) / last: Sacc image ----------
__device__ __forceinline__ void epiB(FragC (&c)[8], const float* __restrict__ b2,
                                     float coef, bool last, float* __restrict__ bounce,
                                     u32 tid, u32 m0, u32 c0) {
    u32 warp = tid >> 5, lane = tid & 31u;
    u32 rowg = warp >> 2, colg = warp & 3u;
    float* bw = bounce + warp*256u;
    u32 row = lane & 15u, cg = lane >> 4;
#pragma unroll
    for (int r2 = 0; r2 < 2; ++r2)
#pragma unroll 1
    for (int t = 0; t < 4; ++t) {
        wmma::store_matrix_sync(bw, c[r2*4 + t], 16, wmma::mem_row_major);
        __syncwarp();
        const float* p = bw + row*16u + cg*8u;
        u32 col = c0 + colg*64u + (u32)t*16u + cg*8u;
        u32 m = m0 + rowg*32u + (u32)r2*16u + row;
        float4 bA = __ldg((const float4*)(b2 + col));
        float4 bB = __ldg((const float4*)(b2 + col + 4));
        float bb[8] = { bA.x, bA.y, bA.z, bA.w, bB.x, bB.y, bB.z, bB.w };
        size_t si = (size_t)m*512u + col;
        float v[8];
#pragma unroll
        for (int j = 0; j < 8; ++j) v[j] = silu(p[j] + bb[j]);
        alignas(16) __half hv[8], lv[8];
        if (!last) {
            float4 s0 = *(float4*)(g_Sacc + si);
            float4 s1 = *(float4*)(g_Sacc + si + 4);
            s0.x += coef*v[0]; s0.y += coef*v[1]; s0.z += coef*v[2]; s0.w += coef*v[3];
            s1.x += coef*v[4]; s1.y += coef*v[5]; s1.z += coef*v[6]; s1.w += coef*v[7];
            *(float4*)(g_Sacc + si)     = s0;
            *(float4*)(g_Sacc + si + 4) = s1;
#pragma unroll
            for (int j = 0; j < 8; ++j) hsplit(v[j], hv[j], lv[j]);
        } else {
            float4 s0 = *(float4*)(g_Sacc + si);
            float4 s1 = *(float4*)(g_Sacc + si + 4);
            float S[8] = { s0.x+v[0], s0.y+v[1], s0.z+v[2], s0.w+v[3],
                           s1.x+v[4], s1.y+v[5], s1.z+v[6], s1.w+v[7] };
#pragma unroll
            for (int j = 0; j < 8; ++j) hsplit(S[j], hv[j], lv[j]);
        }
        *reinterpret_cast<uint4*>(&g_H2h[si])      = *reinterpret_cast<const uint4*>(hv);
        *reinterpret_cast<uint4*>(&g_H2h[HN + si]) = *reinterpret_cast<const uint4*>(lv);
        __syncwarp();
    }
}

// ---------- epilogue C (fused h1_pre update) / also init (plain write) ----------
__device__ __forceinline__ void epiC(FragC (&c)[8], const float* __restrict__ addv,
                                     float coef, bool init, float* __restrict__ bounce,
                                     u32 tid, u32 m0, u32 c0) {
    u32 warp = tid >> 5, lane = tid & 31u;
    u32 rowg = warp >> 2, colg = warp & 3u;
    float* bw = bounce + warp*256u;
    u32 row = lane & 15u, cg = lane >> 4;
#pragma unroll
    for (int r2 = 0; r2 < 2; ++r2)
#pragma unroll 1
    for (int t = 0; t < 4; ++t) {
        wmma::store_matrix_sync(bw, c[r2*4 + t], 16, wmma::mem_row_major);
        __syncwarp();
        const float* p = bw + row*16u + cg*8u;
        u32 col = c0 + colg*64u + (u32)t*16u + cg*8u;
        u32 m = m0 + rowg*32u + (u32)r2*16u + row;
        float4 bA = __ldg((const float4*)(addv + col));
        float4 bB = __ldg((const float4*)(addv + col + 4));
        float bb[8] = { bA.x, bA.y, bA.z, bA.w, bB.x, bB.y, bB.z, bB.w };
        size_t si = (size_t)m*512u + col;
        float hp[8];
        if (init) {
#pragma unroll
            for (int j = 0; j < 8; ++j) hp[j] = p[j] + bb[j];
        } else {
            float4 h0 = *(float4*)(g_h1p + si);
            float4 h1 = *(float4*)(g_h1p + si + 4);
            float ho[8] = { h0.x, h0.y, h0.z, h0.w, h1.x, h1.y, h1.z, h1.w };
#pragma unroll
            for (int j = 0; j < 8; ++j) hp[j] = ho[j] + coef * (p[j] + bb[j]);
        }
        *(float4*)(g_h1p + si)     = make_float4(hp[0], hp[1], hp[2], hp[3]);
        *(float4*)(g_h1p + si + 4) = make_float4(hp[4], hp[5], hp[6], hp[7]);
        alignas(16) bf16 hv[8], lv[8];
#pragma unroll
        for (int j = 0; j < 8; ++j) bsplit(silu(hp[j]), hv[j], lv[j]);
        *reinterpret_cast<uint4*>(&g_H1[si])      = *reinterpret_cast<const uint4*>(hv);
        *reinterpret_cast<uint4*>(&g_H1[HN + si]) = *reinterpret_cast<const uint4*>(lv);
        __syncwarp();
    }
}

// ---------- final epilogue: out = state0 + Sacc@W3 + 2*b3 ----------
__device__ __forceinline__ void epiF(FragC (&c)[8], const float* __restrict__ b3,
                                     const float* __restrict__ state0,
                                     float* __restrict__ out,
                                     float* __restrict__ bounce, u32 tid, u32 m0, u32 c0) {
    u32 warp = tid >> 5, lane = tid & 31u;
    u32 rowg = warp >> 2, colg = warp & 3u;
    float* bw = bounce + warp*256u;
    u32 row = lane & 15u, cg = lane >> 4;
#pragma unroll
    for (int r2 = 0; r2 < 2; ++r2)
#pragma unroll 1
    for (int t = 0; t < 2; ++t) {
        wmma::store_matrix_sync(bw, c[r2*2 + t], 16, wmma::mem_row_major);
        __syncwarp();
        const float* p = bw + row*16u + cg*8u;
        u32 col = c0 + colg*32u + (u32)t*16u + cg*8u;
        u32 m = m0 + rowg*32u + (u32)r2*16u + row;
        size_t si = (size_t)m*256u + col;
        float4 bA = __ldg((const float4*)(b3 + col));
        float4 bB = __ldg((const float4*)(b3 + col + 4));
        float4 s0 = __ldg((const float4*)(state0 + si));
        float4 s1 = __ldg((const float4*)(state0 + si + 4));
        float bb[8] = { bA.x, bA.y, bA.z, bA.w, bB.x, bB.y, bB.z, bB.w };
        float ss[8] = { s0.x, s0.y, s0.z, s0.w, s1.x, s1.y, s1.z, s1.w };
        float o[8];
#pragma unroll
        for (int j = 0; j < 8; ++j) o[j] = ss[j] + p[j] + 2.0f * bb[j];
        *(float4*)(out + si)     = make_float4(o[0], o[1], o[2], o[3]);
        *(float4*)(out + si + 4) = make_float4(o[4], o[5], o[6], o[7]);
        __syncwarp();
    }
}

// ---------- main kernel ----------
__global__ void __launch_bounds__(THREADS, 2)
ode_mma(const float* __restrict__ b1, const float* __restrict__ b2,
        const float* __restrict__ b3, const float* __restrict__ state0,
        float* __restrict__ out) {
    extern __shared__ __align__(16) u8 smp[];
    u32 smb = (u32)__cvta_generic_to_shared(smp);
    u32 tid = threadIdx.x;
    u32 cta = blockIdx.x;
    u32 m0   = (cta >> 1) * 64u;
    u32 half = cta & 1u;
    float* bounce = (float*)(smp + SNC_B);

    FragC c[8];
    int phase = 0;

    // init: h1_pre = X@W1 + b1  (bf16 3-term; emits H1(0) image)
    run_layer<bf16, 12, 4, 256u, 3>(g_X, 384u, XN, g_W1, 384u, 196608u, half*256u,
                                    m0, smp, smb, tid, c);
    epiC(c, b1, 0.0f, true, bounce, tid, m0, half*256u);
    pair_sync(cta, ++phase, tid);

#pragma unroll 1
    for (int it = 0; it < NITER; ++it) {
        const float coef = (it == NITER - 1) ? 1.0f : DT;
        const bool last = (it == NITER - 1);
        // H2 = silu(H1@W2 + b2)  (bf16 3-term); Sacc += coef*H2 (last: Sacc image)
        run_layer<bf16, 16, 4, 256u, 3>(g_H1, 512u, HN, g_W2, 512u, 262144u, half*256u,
                                        m0, smp, smb, tid, c);
        epiB(c, b2, coef, last, bounce, tid, m0, half*256u);
        pair_sync(cta, ++phase, tid);
        if (!last) {
            // h1_pre += coef*(H2@W31 + c31)  (fp16 2-term, dt-damped)
            run_layer<__half, 16, 4, 256u, 2>(g_H2h, 512u, HN, g_W31h, 512u, 0u, half*256u,
                                              m0, smp, smb, tid, c);
            epiC(c, g_c31, coef, false, bounce, tid, m0, half*256u);
            pair_sync(cta, ++phase, tid);
        }
    }

    // final: out = state0 + Sacc@W3 + 2*b3   (fp16 3-term; Sacc image in g_H2h)
    run_layer<__half, 16, 2, 128u, 3>(g_H2h, 512u, HN, g_W3h, 512u, 131072u, half*128u,
                                      m0, smp, smb, tid, c);
    epiF(c, b3, state0, out, bounce, tid, m0, half*128u);
}

extern "C" void kernel_launch(void* const* d_in, const int* in_sizes, int n_in,
                              void* d_out, int out_size) {
    const float* state = (const float*)d_in[0];
    const float* user  = (const float*)d_in[1];
    const float* W1    = (const float*)d_in[2];
    const float* b1    = (const float*)d_in[3];
    const float* W2    = (const float*)d_in[4];
    const float* b2    = (const float*)d_in[5];
    const float* W3    = (const float*)d_in[6];
    const float* b3    = (const float*)d_in[7];
    float* out = (float*)d_out;

    prep_w31<<<513, 512>>>(W1, W3, b3);
    prep_all<<<16384, 256>>>(state, user, W1, W2, W3);
    cudaFuncSetAttribute(ode_mma, cudaFuncAttributeMaxDynamicSharedMemorySize, SMEM_SZ);
    ode_mma<<<256, THREADS, SMEM_SZ>>>(b1, b2, b3, state, out);
}

// round 17
// speedup vs baseline: 1.3358x; 1.1276x over previous
#include <cuda_runtime.h>
#include <cuda_bf16.h>
#include <cuda_fp16.h>
#include <mma.h>

using namespace nvcuda;
typedef unsigned int u32;
typedef unsigned char u8;
typedef __nv_bfloat16 bf16;

#define NITER 21        // floor(1/0.05)=20 scaled steps + 1 unscaled add
#define DT    0.05f
#define THREADS 256

// ---- global images ----
#define XN (8192u*384u)
#define HN (8192u*512u)
__device__ __align__(16) bf16   g_X  [2u*XN];       // [m][384] bf16 hi | lo (init only)
__device__ __align__(16) __half g_H1h[2u*HN];       // [m][512] fp16 hi | lo
__device__ __align__(16) __half g_H2h[2u*HN];       // [m][512] fp16 hi | lo (H2 / Sacc image)
__device__ __align__(16) bf16   g_W1 [2u*196608u];  // [512 n][384 k] bf16 hi | lo
__device__ __align__(16) __half g_W2h[262144u];     // [512 n][512 k] fp16 single
__device__ __align__(16) __half g_W31h[262144u];    // fused W3@W1s, fp16 single
__device__ __align__(16) __half g_W3h[2u*131072u];  // [256 n][512 k] fp16 hi | lo
__device__ float g_W31f[262144u];                   // fp32 W3@W1s [k=512][n=512]
__device__ float g_c31 [512u];                      // b3@W1s
__device__ float g_h1p [8192u*512u];                // evolving h1_pre, fp32
__device__ float g_Sacc[8192u*512u];                // sum coef_i * H2_i, fp32
__device__ u32   g_flag[256];                       // pair handshake counters

// ---- smem (bytes). rows padded to 40 elems (80B): LDSM conflict-free ----
#define SA_B    0u
#define SA_PRT  5120u
#define SA_BUF  10240u
#define SB_B    20480u
#define SNC_B   102400u
#define SMEM_SZ 110592

using FragC = wmma::fragment<wmma::accumulator, 16, 16, 16, float>;

__device__ __forceinline__ void cp16ca(u32 dst, const void* src) {
    asm volatile("cp.async.ca.shared.global [%0], [%1], 16;" :: "r"(dst), "l"(src));
}
__device__ __forceinline__ void cp16cg(u32 dst, const void* src) {
    asm volatile("cp.async.cg.shared.global [%0], [%1], 16;" :: "r"(dst), "l"(src));
}
#define CP_COMMIT() asm volatile("cp.async.commit_group;" ::: "memory")
#define CP_WAIT0()  asm volatile("cp.async.wait_group 0;" ::: "memory")

__device__ __forceinline__ void bsplit(float v, bf16& h, bf16& l) {
    h = __float2bfloat16(v);
    l = __float2bfloat16(v - __bfloat162float(h));
}
__device__ __forceinline__ void hsplit(float v, __half& h, __half& l) {
    h = __float2half_rn(v);
    l = __float2half_rn(v - __half2float(h));
}
__device__ __forceinline__ float silu(float x) { return x / (1.0f + __expf(-x)); }

// ---------- prep 1: fused weight W31 = W3 @ W1s, c31 = b3 @ W1s (fp32) ----------
__global__ void prep_w31(const float* __restrict__ W1, const float* __restrict__ W3,
                         const float* __restrict__ b3) {
    u32 n = threadIdx.x;
    u32 k = blockIdx.x;
    float a = 0.0f;
    if (k < 512u) {
#pragma unroll 8
        for (u32 s = 0; s < 256u; ++s) a += W3[k*256u + s] * W1[s*512u + n];
        g_W31f[k*512u + n] = a;
    } else {
#pragma unroll 8
        for (u32 s = 0; s < 256u; ++s) a += b3[s] * W1[s*512u + n];
        g_c31[n] = a;
    }
}

// ---------- prep 2: split images, X image, zero Sacc/flags ----------
__global__ void prep_all(const float* __restrict__ state, const float* __restrict__ user,
                         const float* __restrict__ W1, const float* __restrict__ W2,
                         const float* __restrict__ W3) {
    u32 i = blockIdx.x * blockDim.x + threadIdx.x;
    if (i < 256u) g_flag[i] = 0u;
    if (i < 8192u*512u) g_Sacc[i] = 0.0f;
    if (i < 196608u) {
        u32 k = i >> 9, n = i & 511u;
        bf16 h, l; bsplit(W1[i], h, l);
        g_W1[n*384u + k] = h; g_W1[196608u + n*384u + k] = l;
    }
    if (i < 262144u) {
        u32 k = i >> 9, n = i & 511u;
        g_W2h [n*512u + k] = __float2half_rn(W2[i]);       // fp16 single
        g_W31h[n*512u + k] = __float2half_rn(g_W31f[i]);   // fp16 single
    }
    if (i < 131072u) {
        u32 k = i >> 8, n = i & 255u;
        __half h, l; hsplit(W3[i], h, l);
        g_W3h[n*512u + k] = h; g_W3h[131072u + n*512u + k] = l;
    }
    if (i < 8192u*384u) {
        u32 m = i / 384u, f = i - m*384u;
        float v = (f < 256u) ? state[m*256u + f] : user[m*128u + (f - 256u)];
        bf16 h, l; bsplit(v, h, l);
        g_X[i] = h; g_X[XN + i] = l;
    }
}

// ---------- pair sync ----------
__device__ __forceinline__ void pair_sync(u32 cta, int phase, u32 tid) {
    __syncthreads();
    if (tid == 0) {
        __threadfence();
        atomicAdd(&g_flag[cta], 1u);
        u32 v;
        do {
            asm volatile("ld.global.acquire.gpu.u32 %0, [%1];"
                         : "=r"(v) : "l"(&g_flag[cta ^ 1u]));
        } while ((int)v < phase);
    }
    __syncthreads();
}

// ---------- staging (element size 2B) ----------
__device__ __forceinline__ void stageA(u32 dst, const void* img,
                                       u32 ldk, u32 partN, u32 m0, u32 k0, u32 tid) {
#pragma unroll
    for (u32 e = 0; e < 2; ++e) {
        u32 idx = tid + e*256u;
        u32 p = idx >> 8, r = (idx >> 2) & 63u, ch = idx & 3u;
        cp16cg(dst + p*SA_PRT + r*80u + ch*16u,
               (const u8*)img + 2u*((size_t)p*partN + (size_t)(m0 + r)*ldk + k0 + ch*8u));
    }
}
template<u32 NR, int BP>
__device__ __forceinline__ void stageB(u32 dst, const void* img,
                                       u32 ldk, u32 partN, u32 n0, u32 k0, u32 tid) {
#pragma unroll
    for (u32 e = 0; e < NR*BP/64u; ++e) {
        u32 idx = tid + e*256u;
        u32 p = idx / (NR*4u), rem = idx % (NR*4u), n = rem >> 2, ch = rem & 3u;
        cp16ca(dst + p*(NR*80u) + n*80u + ch*16u,
               (const u8*)img + 2u*((size_t)p*partN + (size_t)(n0 + n)*ldk + k0 + ch*8u));
    }
}

// ---------- GEMM: C[64 x NR] = A[64 x NST*32] * B^T ----------
// TERMS=3: ah*bh + ah*bl + al*bh (B hi|lo). TERMS=2: ah*b + al*b (B single).
template<typename T, int NST, int NT, u32 NR, int TERMS>
__device__ __forceinline__ void run_layer(
    const T* __restrict__ Aimg, u32 aldk, u32 apartN,
    const T* __restrict__ Bimg, u32 bldk, u32 bpartN, u32 n0,
    u32 m0, u8* smp, u32 smb, u32 tid, FragC (&c)[8])
{
    constexpr int BP = (TERMS == 3) ? 2 : 1;
    constexpr u32 BUFSZ = NR * 80u * (u32)BP;
#pragma unroll
    for (int i = 0; i < 2*NT; ++i) wmma::fill_fragment(c[i], 0.0f);
    const u32 warp = tid >> 5;
    const u32 rowg = warp >> 2, colg = warp & 3u;

    stageA(smb + SA_B, Aimg, aldk, apartN, m0, 0u, tid);
    stageB<NR, BP>(smb + SB_B, Bimg, bldk, bpartN, n0, 0u, tid);
    CP_COMMIT();
#pragma unroll 1
    for (int st = 0; st < NST; ++st) {
        const u32 buf = (u32)st & 1u;
        CP_WAIT0();
        __syncthreads();
        if (st + 1 < NST) {
            stageA(smb + SA_B + (buf^1u)*SA_BUF, Aimg, aldk, apartN, m0, (u32)(st+1)*32u, tid);
            stageB<NR, BP>(smb + SB_B + (buf^1u)*BUFSZ, Bimg, bldk, bpartN, n0, (u32)(st+1)*32u, tid);
            CP_COMMIT();
        }
        const T* sa = (const T*)(smp + SA_B + buf*SA_BUF);
        const T* sb = (const T*)(smp + SB_B + buf*BUFSZ);
#pragma unroll
        for (int ks = 0; ks < 2; ++ks) {
            wmma::fragment<wmma::matrix_a, 16, 16, 16, T, wmma::row_major> ah[2], al[2];
#pragma unroll
            for (int r2 = 0; r2 < 2; ++r2) {
                const T* ap = sa + (rowg*32u + (u32)r2*16u)*40u + (u32)ks*16u;
                wmma::load_matrix_sync(ah[r2], ap, 40);
                wmma::load_matrix_sync(al[r2], ap + 2560u, 40);       // A lo (+5120B)
            }
#pragma unroll
            for (int t = 0; t < NT; ++t) {
                const T* bp = sb + (colg*(u32)NT*16u + (u32)t*16u)*40u + (u32)ks*16u;
                wmma::fragment<wmma::matrix_b, 16, 16, 16, T, wmma::col_major> bh, bl;
                wmma::load_matrix_sync(bh, bp, 40);
                if (TERMS == 3) wmma::load_matrix_sync(bl, bp + (NR*40u), 40);
#pragma unroll
                for (int r2 = 0; r2 < 2; ++r2) {
                    wmma::mma_sync(c[r2*NT + t], ah[r2], bh, c[r2*NT + t]);
                    if (TERMS == 3) wmma::mma_sync(c[r2*NT + t], ah[r2], bl, c[r2*NT + t]);
                    wmma::mma_sync(c[r2*NT + t], al[r2], bh, c[r2*NT + t]);
                }
            }
        }
    }
}

// ---------- epilogue B (layer-2): silu + fp16 H2 image (+Sacc RMW) / last: Sacc image ----------
__device__ __forceinline__ void epiB(FragC (&c)[8], const float* __restrict__ b2,
                                     float coef, bool last, float* __restrict__ bounce,
                                     u32 tid, u32 m0, u32 c0) {
    u32 warp = tid >> 5, lane = tid & 31u;
    u32 rowg = warp >> 2, colg = warp & 3u;
    float* bw = bounce + warp*256u;
    u32 row = lane & 15u, cg = lane >> 4;
#pragma unroll
    for (int r2 = 0; r2 < 2; ++r2)
#pragma unroll 1
    for (int t = 0; t < 4; ++t) {
        wmma::store_matrix_sync(bw, c[r2*4 + t], 16, wmma::mem_row_major);
        __syncwarp();
        const float* p = bw + row*16u + cg*8u;
        u32 col = c0 + colg*64u + (u32)t*16u + cg*8u;
        u32 m = m0 + rowg*32u + (u32)r2*16u + row;
        float4 bA = __ldg((const float4*)(b2 + col));
        float4 bB = __ldg((const float4*)(b2 + col + 4));
        float bb[8] = { bA.x, bA.y, bA.z, bA.w, bB.x, bB.y, bB.z, bB.w };
        size_t si = (size_t)m*512u + col;
        float v[8];
#pragma unroll
        for (int j = 0; j < 8; ++j) v[j] = silu(p[j] + bb[j]);
        alignas(16) __half hv[8], lv[8];
        if (!last) {
            float4 s0 = *(float4*)(g_Sacc + si);
            float4 s1 = *(float4*)(g_Sacc + si + 4);
            s0.x += coef*v[0]; s0.y += coef*v[1]; s0.z += coef*v[2]; s0.w += coef*v[3];
            s1.x += coef*v[4]; s1.y += coef*v[5]; s1.z += coef*v[6]; s1.w += coef*v[7];
            *(float4*)(g_Sacc + si)     = s0;
            *(float4*)(g_Sacc + si + 4) = s1;
#pragma unroll
            for (int j = 0; j < 8; ++j) hsplit(v[j], hv[j], lv[j]);
        } else {
            float4 s0 = *(float4*)(g_Sacc + si);
            float4 s1 = *(float4*)(g_Sacc + si + 4);
            float S[8] = { s0.x+v[0], s0.y+v[1], s0.z+v[2], s0.w+v[3],
                           s1.x+v[4], s1.y+v[5], s1.z+v[6], s1.w+v[7] };
#pragma unroll
            for (int j = 0; j < 8; ++j) hsplit(S[j], hv[j], lv[j]);
        }
        *reinterpret_cast<uint4*>(&g_H2h[si])      = *reinterpret_cast<const uint4*>(hv);
        *reinterpret_cast<uint4*>(&g_H2h[HN + si]) = *reinterpret_cast<const uint4*>(lv);
        __syncwarp();
    }
}

// ---------- epilogue C (fused h1_pre update) / also init (plain write) ----------
__device__ __forceinline__ void epiC(FragC (&c)[8], const float* __restrict__ addv,
                                     float coef, bool init, float* __restrict__ bounce,
                                     u32 tid, u32 m0, u32 c0) {
    u32 warp = tid >> 5, lane = tid & 31u;
    u32 rowg = warp >> 2, colg = warp & 3u;
    float* bw = bounce + warp*256u;
    u32 row = lane & 15u, cg = lane >> 4;
#pragma unroll
    for (int r2 = 0; r2 < 2; ++r2)
#pragma unroll 1
    for (int t = 0; t < 4; ++t) {
        wmma::store_matrix_sync(bw, c[r2*4 + t], 16, wmma::mem_row_major);
        __syncwarp();
        const float* p = bw + row*16u + cg*8u;
        u32 col = c0 + colg*64u + (u32)t*16u + cg*8u;
        u32 m = m0 + rowg*32u + (u32)r2*16u + row;
        float4 bA = __ldg((const float4*)(addv + col));
        float4 bB = __ldg((const float4*)(addv + col + 4));
        float bb[8] = { bA.x, bA.y, bA.z, bA.w, bB.x, bB.y, bB.z, bB.w };
        size_t si = (size_t)m*512u + col;
        float hp[8];
        if (init) {
#pragma unroll
            for (int j = 0; j < 8; ++j) hp[j] = p[j] + bb[j];
        } else {
            float4 h0 = *(float4*)(g_h1p + si);
            float4 h1 = *(float4*)(g_h1p + si + 4);
            float ho[8] = { h0.x, h0.y, h0.z, h0.w, h1.x, h1.y, h1.z, h1.w };
#pragma unroll
            for (int j = 0; j < 8; ++j) hp[j] = ho[j] + coef * (p[j] + bb[j]);
        }
        *(float4*)(g_h1p + si)     = make_float4(hp[0], hp[1], hp[2], hp[3]);
        *(float4*)(g_h1p + si + 4) = make_float4(hp[4], hp[5], hp[6], hp[7]);
        alignas(16) __half hv[8], lv[8];
#pragma unroll
        for (int j = 0; j < 8; ++j) hsplit(silu(hp[j]), hv[j], lv[j]);
        *reinterpret_cast<uint4*>(&g_H1h[si])      = *reinterpret_cast<const uint4*>(hv);
        *reinterpret_cast<uint4*>(&g_H1h[HN + si]) = *reinterpret_cast<const uint4*>(lv);
        __syncwarp();
    }
}

// ---------- final epilogue: out = state0 + Sacc@W3 + 2*b3 ----------
__device__ __forceinline__ void epiF(FragC (&c)[8], const float* __restrict__ b3,
                                     const float* __restrict__ state0,
                                     float* __restrict__ out,
                                     float* __restrict__ bounce, u32 tid, u32 m0, u32 c0) {
    u32 warp = tid >> 5, lane = tid & 31u;
    u32 rowg = warp >> 2, colg = warp & 3u;
    float* bw = bounce + warp*256u;
    u32 row = lane & 15u, cg = lane >> 4;
#pragma unroll
    for (int r2 = 0; r2 < 2; ++r2)
#pragma unroll 1
    for (int t = 0; t < 2; ++t) {
        wmma::store_matrix_sync(bw, c[r2*2 + t], 16, wmma::mem_row_major);
        __syncwarp();
        const float* p = bw + row*16u + cg*8u;
        u32 col = c0 + colg*32u + (u32)t*16u + cg*8u;
        u32 m = m0 + rowg*32u + (u32)r2*16u + row;
        size_t si = (size_t)m*256u + col;
        float4 bA = __ldg((const float4*)(b3 + col));
        float4 bB = __ldg((const float4*)(b3 + col + 4));
        float4 s0 = __ldg((const float4*)(state0 + si));
        float4 s1 = __ldg((const float4*)(state0 + si + 4));
        float bb[8] = { bA.x, bA.y, bA.z, bA.w, bB.x, bB.y, bB.z, bB.w };
        float ss[8] = { s0.x, s0.y, s0.z, s0.w, s1.x, s1.y, s1.z, s1.w };
        float o[8];
#pragma unroll
        for (int j = 0; j < 8; ++j) o[j] = ss[j] + p[j] + 2.0f * bb[j];
        *(float4*)(out + si)     = make_float4(o[0], o[1], o[2], o[3]);
        *(float4*)(out + si + 4) = make_float4(o[4], o[5], o[6], o[7]);
        __syncwarp();
    }
}

// ---------- main kernel ----------
__global__ void __launch_bounds__(THREADS, 2)
ode_mma(const float* __restrict__ b1, const float* __restrict__ b2,
        const float* __restrict__ b3, const float* __restrict__ state0,
        float* __restrict__ out) {
    extern __shared__ __align__(16) u8 smp[];
    u32 smb = (u32)__cvta_generic_to_shared(smp);
    u32 tid = threadIdx.x;
    u32 cta = blockIdx.x;
    u32 m0   = (cta >> 1) * 64u;
    u32 half = cta & 1u;
    float* bounce = (float*)(smp + SNC_B);

    FragC c[8];
    int phase = 0;

    // init: h1_pre = X@W1 + b1  (bf16 3-term; emits H1(0) fp16 image)
    run_layer<bf16, 12, 4, 256u, 3>(g_X, 384u, XN, g_W1, 384u, 196608u, half*256u,
                                    m0, smp, smb, tid, c);
    epiC(c, b1, 0.0f, true, bounce, tid, m0, half*256u);
    pair_sync(cta, ++phase, tid);

#pragma unroll 1
    for (int it = 0; it < NITER; ++it) {
        const float coef = (it == NITER - 1) ? 1.0f : DT;
        const bool last = (it == NITER - 1);
        // H2 = silu(H1@W2 + b2)  (fp16 2-term); Sacc += coef*H2 (last: Sacc image)
        run_layer<__half, 16, 4, 256u, 2>(g_H1h, 512u, HN, g_W2h, 512u, 0u, half*256u,
                                          m0, smp, smb, tid, c);
        epiB(c, b2, coef, last, bounce, tid, m0, half*256u);
        pair_sync(cta, ++phase, tid);
        if (!last) {
            // h1_pre += coef*(H2@W31 + c31)  (fp16 2-term, dt-damped)
            run_layer<__half, 16, 4, 256u, 2>(g_H2h, 512u, HN, g_W31h, 512u, 0u, half*256u,
                                              m0, smp, smb, tid, c);
            epiC(c, g_c31, coef, false, bounce, tid, m0, half*256u);
            pair_sync(cta, ++phase, tid);
        }
    }

    // final: out = state0 + Sacc@W3 + 2*b3   (fp16 3-term; Sacc image in g_H2h)
    run_layer<__half, 16, 2, 128u, 3>(g_H2h, 512u, HN, g_W3h, 512u, 131072u, half*128u,
                                      m0, smp, smb, tid, c);
    epiF(c, b3, state0, out, bounce, tid, m0, half*128u);
}

extern "C" void kernel_launch(void* const* d_in, const int* in_sizes, int n_in,
                              void* d_out, int out_size) {
    const float* state = (const float*)d_in[0];
    const float* user  = (const float*)d_in[1];
    const float* W1    = (const float*)d_in[2];
    const float* b1    = (const float*)d_in[3];
    const float* W2    = (const float*)d_in[4];
    const float* b2    = (const float*)d_in[5];
    const float* W3    = (const float*)d_in[6];
    const float* b3    = (const float*)d_in[7];
    float* out = (float*)d_out;

    prep_w31<<<513, 512>>>(W1, W3, b3);
    prep_all<<<16384, 256>>>(state, user, W1, W2, W3);
    cudaFuncSetAttribute(ode_mma, cudaFuncAttributeMaxDynamicSharedMemorySize, SMEM_SZ);
    ode_mma<<<256, THREADS, SMEM_SZ>>>(b1, b2, b3, state, out);
}